// round 15
// baseline (speedup 1.0000x reference)
#include <cuda_runtime.h>
#include <cstdint>

#define NB 256
#define NT 512
#define NI 300
#define NH 128

typedef unsigned long long u64t;

// Precomputed input projections xp[b][t][h], padded by 8 timesteps so the
// distance-4 register prefetch in the scan can overrun harmlessly.
__device__ float g_xp[(NB * NT + 8) * NH];
// W_ih transposed to k-major and pre-duplicated as {w,w} u64 pairs:
// g_wih2[k * NH + n] = {Wih[n][k], Wih[n][k]}. 300*128*8 = 307KB (L2-resident).
__device__ u64t g_wih2[NI * NH];

// ---------------- packed f32x2 helpers (sm_103a) ----------------
__device__ __forceinline__ u64t pack2(float lo, float hi) {
    u64t r;
    asm("mov.b64 %0, {%1, %2};" : "=l"(r) : "f"(lo), "f"(hi));
    return r;
}
__device__ __forceinline__ void unpack2(u64t v, float& lo, float& hi) {
    asm("mov.b64 {%0, %1}, %2;" : "=f"(lo), "=f"(hi) : "l"(v));
}
__device__ __forceinline__ void ffma2(u64t& d, u64t a, u64t b) {
    asm("fma.rn.f32x2 %0, %1, %2, %0;" : "+l"(d) : "l"(a), "l"(b));
}
__device__ __forceinline__ void cp_async4(uint32_t s, const void* g) {
    asm volatile("cp.async.ca.shared.global [%0], [%1], 4;" :: "r"(s), "l"(g));
}
__device__ __forceinline__ void cp_async16(uint32_t s, const void* g) {
    asm volatile("cp.async.cg.shared.global [%0], [%1], 16;" :: "r"(s), "l"(g));
}
// fast tanh: 1 - 2/(e^{2x}+1) via MUFU ex2 + rcp (~1e-6 abs err)
__device__ __forceinline__ float tanh_fast(float x) {
    float e;
    asm("ex2.approx.f32 %0, %1;" : "=f"(e) : "f"(x * 2.885390082f));  // 2*log2(e)
    float r;
    asm("rcp.approx.f32 %0, %1;" : "=f"(r) : "f"(e + 1.0f));
    return fmaf(-2.0f, r, 1.0f);
}

// ---------------------------------------------------------------------------
// Phase 0: duplicate W_ih into k-major {w,w} pairs (one-time, ~us)
// ---------------------------------------------------------------------------
__global__ void dup_wih_kernel(const float* __restrict__ Wih) {
    int idx = blockIdx.x * blockDim.x + threadIdx.x;   // over NI*NH
    if (idx < NI * NH) {
        int k = idx >> 7;          // / NH
        int n = idx & (NH - 1);
        float w = Wih[n * NI + k];
        g_wih2[idx] = pack2(w, w);
    }
}

// ---------------------------------------------------------------------------
// Phase 1: xp = x @ W_ih^T + (b_ih + b_hh)
// BM=BN=128, BK=20, 256 threads, 8x8 micro-tile, occupancy 2.
// ROUND-15: B tiles come from g_wih2 (pre-duplicated) via cp.async.16 into
// double-buffered dynamic smem -> inner loop is 6 LDS.128 + 32 FFMA2 with
// ZERO pack MOVs (R6 had 8 pack2 per kk = 25% issue overhead + a dependency
// hop). No register staging (the R9 spill trap).
// ---------------------------------------------------------------------------
#define BM 128
#define BN 128
#define BK 20
#define BMP (BM + 4)
#define NTILES (NI / BK)

#define XS_BYTES (2 * BK * BMP * 4)            // 21120
#define WS_BYTES (2 * BK * BN * 8)             // 40960
#define GEMM_SMEM (XS_BYTES + WS_BYTES)        // 62080

__global__ __launch_bounds__(256, 2) void gemm_xp_kernel(
    const float* __restrict__ x,
    const float* __restrict__ bih, const float* __restrict__ bhh)
{
    extern __shared__ __align__(16) char smem_raw[];
    float (*xs)[BK][BMP] = (float (*)[BK][BMP])smem_raw;
    u64t  (*ws2)[BK][BN] = (u64t (*)[BK][BN])(smem_raw + XS_BYTES);
    __shared__ float bias_s[NH];

    const int tid = threadIdx.x;
    const int m0 = blockIdx.x * BM;
    if (tid < NH) bias_s[tid] = bih[tid] + bhh[tid];

    const int tr = tid >> 4;   // m rows tr*8 .. +7
    const int tc = tid & 15;   // n cols tc*8 .. +7

    // x-tile load map: idx = tid + it*256 -> (r, kk)
    uint32_t offSx[10];
    int offGx[10];
#pragma unroll
    for (int it = 0; it < 10; it++) {
        int idx = tid + it * 256;
        int r = idx / BK, kk = idx % BK;
        offSx[it] = (uint32_t)(kk * BMP + r) * 4u;
        offGx[it] = r * NI + kk;
    }

    const uint32_t xsb[2] = {
        (uint32_t)__cvta_generic_to_shared(&xs[0][0][0]),
        (uint32_t)__cvta_generic_to_shared(&xs[1][0][0])};
    const uint32_t wsb[2] = {
        (uint32_t)__cvta_generic_to_shared(&ws2[0][0][0]),
        (uint32_t)__cvta_generic_to_shared(&ws2[1][0][0])};

    const float* xg = x + (long)m0 * NI;

    u64t acc2[4][8];   // [m-pair][n]
#pragma unroll
    for (int mp = 0; mp < 4; mp++)
#pragma unroll
        for (int n = 0; n < 8; n++) acc2[mp][n] = 0ull;

    // issue tile `tile` into buffer `bf`
#define ISSUE_TILE(tile, bf)                                              \
    do {                                                                  \
        const float* xt_ = xg + (tile) * BK;                              \
        _Pragma("unroll")                                                 \
        for (int it = 0; it < 10; it++)                                   \
            cp_async4(xsb[bf] + offSx[it], xt_ + offGx[it]);              \
        const u64t* wt_ = g_wih2 + (tile) * BK * NH;                      \
        _Pragma("unroll")                                                 \
        for (int it = 0; it < 5; it++)                                    \
            cp_async16(wsb[bf] + (uint32_t)(tid * 16 + it * 4096),        \
                       wt_ + tid * 2 + it * 512);                         \
        asm volatile("cp.async.commit_group;");                           \
    } while (0)

    ISSUE_TILE(0, 0);

    for (int tile = 0; tile < NTILES; tile++) {
        int buf = tile & 1;
        if (tile + 1 < NTILES) {
            ISSUE_TILE(tile + 1, buf ^ 1);
            asm volatile("cp.async.wait_group 1;");
        } else {
            asm volatile("cp.async.wait_group 0;");
        }
        __syncthreads();

        const float(*xsp)[BMP] = xs[buf];
        const u64t(*wsp)[BN] = ws2[buf];
#pragma unroll 4
        for (int kk = 0; kk < BK; kk++) {
            // A: 4 natural m-pairs
            ulonglong2 aq0 = *(const ulonglong2*)&xsp[kk][tr * 8];
            ulonglong2 aq1 = *(const ulonglong2*)&xsp[kk][tr * 8 + 4];
            u64t ap[4] = {aq0.x, aq0.y, aq1.x, aq1.y};
            // B: 8 pre-duplicated {w,w} pairs
            const u64t* wrow = &wsp[kk][tc * 8];
            ulonglong2 bq0 = *(const ulonglong2*)&wrow[0];
            ulonglong2 bq1 = *(const ulonglong2*)&wrow[2];
            ulonglong2 bq2 = *(const ulonglong2*)&wrow[4];
            ulonglong2 bq3 = *(const ulonglong2*)&wrow[6];
            u64t bp[8] = {bq0.x, bq0.y, bq1.x, bq1.y,
                          bq2.x, bq2.y, bq3.x, bq3.y};
#pragma unroll
            for (int mp = 0; mp < 4; mp++)
#pragma unroll
                for (int n = 0; n < 8; n++)
                    ffma2(acc2[mp][n], ap[mp], bp[n]);
        }
        __syncthreads();   // compute done before next ISSUE overwrites buf
    }
#undef ISSUE_TILE

    // epilogue: lo = row tr*8+2mp, hi = row tr*8+2mp+1
#pragma unroll
    for (int mp = 0; mp < 4; mp++) {
        float lo[8], hi[8];
#pragma unroll
        for (int n = 0; n < 8; n++) {
            unpack2(acc2[mp][n], lo[n], hi[n]);
            lo[n] += bias_s[tc * 8 + n];
            hi[n] += bias_s[tc * 8 + n];
        }
        int r0 = m0 + tr * 8 + 2 * mp;
        float4* d0 = (float4*)&g_xp[(long)r0 * NH + tc * 8];
        float4* d1 = (float4*)&g_xp[(long)(r0 + 1) * NH + tc * 8];
        d0[0] = make_float4(lo[0], lo[1], lo[2], lo[3]);
        d0[1] = make_float4(lo[4], lo[5], lo[6], lo[7]);
        d1[0] = make_float4(hi[0], hi[1], hi[2], hi[3]);
        d1[1] = make_float4(hi[4], hi[5], hi[6], hi[7]);
    }
}

// ---------------------------------------------------------------------------
// Phase 2: scan. ONE batch row per CTA, 256 CTAs x 256 threads, 2 CTAs/SM.
// ROUND-15: thread (og = tid>>3, kg = tid&7) computes FOUR outputs
// j = og*4..+3 over a 16-wide k-slice k = kg*16..+15:
//   - 4 LDS.128 / thread / step (16KB/step/CTA -> ~128cy/SM, still cheap)
//   - 32 FFMA2 as 4 chains of 8
//   - THREE-stage butterfly over 8 kg-lanes: 4 SHFL, ~6 SEL (was 8/12 with
//     4 dependent stages) -> ~30cy less serial depth, less ALU
//   - distance-4 named-register xp prefetch (round-13 fix kept)
// ---------------------------------------------------------------------------
__global__ __launch_bounds__(256, 2) void rnn_scan_kernel(
    const float* __restrict__ Whh, const float* __restrict__ fcw,
    const float* __restrict__ fcb, float* __restrict__ out)
{
    __shared__ __align__(16) float hbuf[2][NH];

    const int tid = threadIdx.x;
    const int og = tid >> 3;        // 0..31: outputs og*4 .. +3
    const int kg = tid & 7;         // 0..7:  k-slice kg*16 .. +15
    const int b = blockIdx.x;

    const bool b4 = (kg & 4) != 0;
    const bool b2 = (kg & 2) != 0;
    const bool writer = (kg & 1) == 0;
    const int jmine = og * 4 + (b4 ? 2 : 0) + (b2 ? 1 : 0);

    // weights: w2[jl][i] = {W[og*4+jl][kg*16+2i], W[og*4+jl][kg*16+2i+1]}
    u64t w2[4][8];
#pragma unroll
    for (int jl = 0; jl < 4; jl++) {
        const ulonglong2* wp =
            (const ulonglong2*)(Whh + (og * 4 + jl) * NH + kg * 16);
        ulonglong2 v0 = wp[0], v1 = wp[1], v2 = wp[2], v3 = wp[3];
        w2[jl][0] = v0.x; w2[jl][1] = v0.y;
        w2[jl][2] = v1.x; w2[jl][3] = v1.y;
        w2[jl][4] = v2.x; w2[jl][5] = v2.y;
        w2[jl][6] = v3.x; w2[jl][7] = v3.y;
    }

    if (tid < NH) hbuf[0][tid] = 0.f;
    __syncthreads();

    const float* __restrict__ xq = g_xp + (long)b * (NT * NH);

    int cur = 0;

    auto do_step = [&](float xv) {
        const float* hs = &hbuf[cur][kg * 16];
        ulonglong2 hv0 = *(const ulonglong2*)(hs);
        ulonglong2 hv1 = *(const ulonglong2*)(hs + 4);
        ulonglong2 hv2 = *(const ulonglong2*)(hs + 8);
        ulonglong2 hv3 = *(const ulonglong2*)(hs + 12);
        u64t hp[8] = {hv0.x, hv0.y, hv1.x, hv1.y, hv2.x, hv2.y, hv3.x, hv3.y};

        u64t c[4] = {0ull, 0ull, 0ull, 0ull};
#pragma unroll
        for (int i = 0; i < 8; i++) {
            ffma2(c[0], hp[i], w2[0][i]);
            ffma2(c[1], hp[i], w2[1][i]);
            ffma2(c[2], hp[i], w2[2][i]);
            ffma2(c[3], hp[i], w2[3][i]);
        }

        float s0, s1, s2, s3, lo, hi;
        unpack2(c[0], lo, hi); s0 = lo + hi;
        unpack2(c[1], lo, hi); s1 = lo + hi;
        unpack2(c[2], lo, hi); s2 = lo + hi;
        unpack2(c[3], lo, hi); s3 = lo + hi;

        // stage 1 (xor 4): keep outputs {2*b4, 2*b4+1}
        float keep0 = b4 ? s2 : s0;
        float send0 = b4 ? s0 : s2;
        float keep1 = b4 ? s3 : s1;
        float send1 = b4 ? s1 : s3;
        float t10 = keep0 + __shfl_xor_sync(0xffffffffu, send0, 4);
        float t11 = keep1 + __shfl_xor_sync(0xffffffffu, send1, 4);
        // stage 2 (xor 2): keep output 2*b4 + b2 (over b1-parity slices)
        float keep2 = b2 ? t11 : t10;
        float send2 = b2 ? t10 : t11;
        float t2 = keep2 + __shfl_xor_sync(0xffffffffu, send2, 2);
        // stage 3 (xor 1): merge complementary slice halves (plain add)
        float tot = t2 + __shfl_xor_sync(0xffffffffu, t2, 1);

        int nxt = cur ^ 1;
        if (writer) hbuf[nxt][jmine] = tanh_fast(tot + xv);
        __syncthreads();
        cur = nxt;
    };

    // distance-4 prefetch pipeline (g_xp padded -> tail loads safe)
    float pf0 = xq[0 * NH + jmine];
    float pf1 = xq[1 * NH + jmine];
    float pf2 = xq[2 * NH + jmine];
    float pf3 = xq[3 * NH + jmine];

    for (int tb = 0; tb < NT; tb += 4) {
        float n0 = __ldg(&xq[(tb + 4) * NH + jmine]);
        float n1 = __ldg(&xq[(tb + 5) * NH + jmine]);
        float n2 = __ldg(&xq[(tb + 6) * NH + jmine]);
        float n3 = __ldg(&xq[(tb + 7) * NH + jmine]);

        do_step(pf0);
        do_step(pf1);
        do_step(pf2);
        do_step(pf3);

        pf0 = n0; pf1 = n1; pf2 = n2; pf3 = n3;
    }

    // fused FC (128 -> 2): warp 0 -> class 0, warp 1 -> class 1
    if (tid < 64) {
        const int w = tid >> 5, lane = tid & 31;
        const float* h = &hbuf[cur][0];
        float s = 0.f;
#pragma unroll
        for (int kk = 0; kk < NH; kk += 32)
            s += h[kk + lane] * fcw[w * NH + kk + lane];
#pragma unroll
        for (int off = 16; off > 0; off >>= 1)
            s += __shfl_xor_sync(0xffffffffu, s, off);
        if (lane == 0) out[b * 2 + w] = s + fcb[w];
    }
}

// ---------------------------------------------------------------------------
extern "C" void kernel_launch(void* const* d_in, const int* in_sizes, int n_in,
                              void* d_out, int out_size)
{
    const float* x   = (const float*)d_in[0];
    const float* Wih = (const float*)d_in[1];
    const float* Whh = (const float*)d_in[2];
    const float* bih = (const float*)d_in[3];
    const float* bhh = (const float*)d_in[4];
    const float* fcw = (const float*)d_in[5];
    const float* fcb = (const float*)d_in[6];
    float* out = (float*)d_out;

    (void)in_sizes; (void)n_in; (void)out_size;

    cudaFuncSetAttribute(gemm_xp_kernel,
                         cudaFuncAttributeMaxDynamicSharedMemorySize, GEMM_SMEM);

    dup_wih_kernel<<<(NI * NH + 255) / 256, 256>>>(Wih);
    gemm_xp_kernel<<<(NB * NT) / BM, 256, GEMM_SMEM>>>(x, bih, bhh);
    rnn_scan_kernel<<<NB, 256>>>(Whh, fcw, fcb, out);
}

// round 16
// speedup vs baseline: 2.0326x; 2.0326x over previous
#include <cuda_runtime.h>
#include <cstdint>

#define NB 256
#define NT 512
#define NI 300
#define NH 128

typedef unsigned long long u64t;

// Precomputed input projections xp[b][t][h], padded by 8 timesteps so the
// distance-4 register prefetch in the scan can overrun harmlessly.
__device__ float g_xp[(NB * NT + 8) * NH];

// ---------------- packed f32x2 helpers (sm_103a) ----------------
__device__ __forceinline__ u64t pack2(float lo, float hi) {
    u64t r;
    asm("mov.b64 %0, {%1, %2};" : "=l"(r) : "f"(lo), "f"(hi));
    return r;
}
__device__ __forceinline__ void unpack2(u64t v, float& lo, float& hi) {
    asm("mov.b64 {%0, %1}, %2;" : "=f"(lo), "=f"(hi) : "l"(v));
}
__device__ __forceinline__ void ffma2(u64t& d, u64t a, u64t b) {
    asm("fma.rn.f32x2 %0, %1, %2, %0;" : "+l"(d) : "l"(a), "l"(b));
}
__device__ __forceinline__ void cp_async4(uint32_t s, const void* g) {
    asm volatile("cp.async.ca.shared.global [%0], [%1], 4;" :: "r"(s), "l"(g));
}
// fast tanh: 1 - 2/(e^{2x}+1) via MUFU ex2 + rcp (~1e-6 abs err)
__device__ __forceinline__ float tanh_fast(float x) {
    float e;
    asm("ex2.approx.f32 %0, %1;" : "=f"(e) : "f"(x * 2.885390082f));  // 2*log2(e)
    float r;
    asm("rcp.approx.f32 %0, %1;" : "=f"(r) : "f"(e + 1.0f));
    return fmaf(-2.0f, r, 1.0f);
}

// hbuf quad swizzle: logical float j -> stored float index.
// quad q = j>>2 stored at P(q) = (q>>2) | ((q&3)<<3)  (bit-rotate, bijective
// on 0..31). Read pattern (thread kg, chunk i) then hits stored quad kg+8i
// -> the 8 kg lanes cover all 8 bank-quads -> conflict-free LDS.128.
__device__ __forceinline__ int hswz(int j) {
    int q = j >> 2;
    int P = (q >> 2) | ((q & 3) << 3);
    return (P << 2) | (j & 3);
}

// ---------------------------------------------------------------------------
// Phase 1: xp = x @ W_ih^T + (b_ih + b_hh)   — ROUND-6 VERSION (FROZEN:
// two rework attempts regressed via reg spills (R9) and smem bank conflicts
// on duplicated operands (R15); 271us known good)
// ---------------------------------------------------------------------------
#define BM 128
#define BN 128
#define BK 20
#define BMP (BM + 4)
#define NTILES (NI / BK)

__global__ __launch_bounds__(256, 2) void gemm_xp_kernel(
    const float* __restrict__ x, const float* __restrict__ Wih,
    const float* __restrict__ bih, const float* __restrict__ bhh)
{
    __shared__ __align__(16) float xs[2][BK][BMP];
    __shared__ __align__(16) float ws[2][BK][BMP];
    __shared__ float bias_s[NH];

    const int tid = threadIdx.x;
    const int m0 = blockIdx.x * BM;
    if (tid < NH) bias_s[tid] = bih[tid] + bhh[tid];

    const int tr = tid >> 4;
    const int tc = tid & 15;

    uint32_t offS[10];
    int offG[10];
#pragma unroll
    for (int it = 0; it < 10; it++) {
        int idx = tid + it * 256;
        int r = idx / BK, kk = idx % BK;
        offS[it] = (uint32_t)(kk * BMP + r) * 4u;
        offG[it] = r * NI + kk;
    }

    const uint32_t xsb0 = (uint32_t)__cvta_generic_to_shared(&xs[0][0][0]);
    const uint32_t xsb1 = (uint32_t)__cvta_generic_to_shared(&xs[1][0][0]);
    const uint32_t wsb0 = (uint32_t)__cvta_generic_to_shared(&ws[0][0][0]);
    const uint32_t wsb1 = (uint32_t)__cvta_generic_to_shared(&ws[1][0][0]);

    const float* xg = x + (long)m0 * NI;

    u64t acc2[8][4];
#pragma unroll
    for (int i = 0; i < 8; i++)
#pragma unroll
        for (int p = 0; p < 4; p++) acc2[i][p] = 0ull;

#define ISSUE_TILE(tile, xsb, wsb)                                   \
    do {                                                             \
        const float* xt_ = xg + (tile) * BK;                         \
        const float* wt_ = Wih + (tile) * BK;                        \
        _Pragma("unroll")                                            \
        for (int it = 0; it < 10; it++) {                            \
            cp_async4((xsb) + offS[it], xt_ + offG[it]);             \
            cp_async4((wsb) + offS[it], wt_ + offG[it]);             \
        }                                                            \
        asm volatile("cp.async.commit_group;");                      \
    } while (0)

    ISSUE_TILE(0, xsb0, wsb0);

    for (int tile = 0; tile < NTILES; tile++) {
        int buf = tile & 1;
        if (tile + 1 < NTILES) {
            if (buf == 0) ISSUE_TILE(tile + 1, xsb1, wsb1);
            else          ISSUE_TILE(tile + 1, xsb0, wsb0);
            asm volatile("cp.async.wait_group 1;");
        } else {
            asm volatile("cp.async.wait_group 0;");
        }
        __syncthreads();

        const float(*xsp)[BMP] = xs[buf];
        const float(*wsp)[BMP] = ws[buf];
#pragma unroll 4
        for (int kk = 0; kk < BK; kk++) {
            float4 a0 = *(const float4*)&xsp[kk][tr * 8];
            float4 a1 = *(const float4*)&xsp[kk][tr * 8 + 4];
            ulonglong2 bq0 = *(const ulonglong2*)&wsp[kk][tc * 8];
            ulonglong2 bq1 = *(const ulonglong2*)&wsp[kk][tc * 8 + 4];
            u64t bp[4] = {bq0.x, bq0.y, bq1.x, bq1.y};
            float av[8] = {a0.x, a0.y, a0.z, a0.w, a1.x, a1.y, a1.z, a1.w};
#pragma unroll
            for (int i = 0; i < 8; i++) {
                u64t ap = pack2(av[i], av[i]);
#pragma unroll
                for (int p = 0; p < 4; p++)
                    ffma2(acc2[i][p], ap, bp[p]);
            }
        }
        __syncthreads();
    }
#undef ISSUE_TILE

#pragma unroll
    for (int i = 0; i < 8; i++) {
        int r = m0 + tr * 8 + i;
        float* pdst = &g_xp[r * NH + tc * 8];
#pragma unroll
        for (int p = 0; p < 4; p++) {
            float lo, hi;
            unpack2(acc2[i][p], lo, hi);
            float2 v;
            v.x = lo + bias_s[tc * 8 + 2 * p];
            v.y = hi + bias_s[tc * 8 + 2 * p + 1];
            *(float2*)(pdst + 2 * p) = v;
        }
    }
}

// ---------------------------------------------------------------------------
// Phase 2: scan. ONE batch row per CTA, 256 CTAs x 256 threads, 2 CTAs/SM.
// Thread (og = tid>>3, kg = tid&7) computes FOUR outputs j = og*4..+3 over
// a 16-wide k-slice k = kg*16..+15:
//   - 4 LDS.128 / thread / step, CONFLICT-FREE via hswz quad swizzle
//     (R14's layout had a 4-way conflict: 32B-stride addresses)
//   - 32 FFMA2 as 4 chains of 8
//   - 3-stage butterfly over the 8 kg-lanes: 4 SHFL, ~6 SEL
//   - distance-4 named-register xp prefetch (round-13 fix)
// ---------------------------------------------------------------------------
__global__ __launch_bounds__(256, 2) void rnn_scan_kernel(
    const float* __restrict__ Whh, const float* __restrict__ fcw,
    const float* __restrict__ fcb, float* __restrict__ out)
{
    __shared__ __align__(16) float hbuf[2][NH];

    const int tid = threadIdx.x;
    const int og = tid >> 3;        // 0..31: outputs og*4 .. +3
    const int kg = tid & 7;         // 0..7:  k-slice kg*16 .. +15
    const int b = blockIdx.x;

    const bool b4 = (kg & 4) != 0;
    const bool b2 = (kg & 2) != 0;
    const bool writer = (kg & 1) == 0;
    const int jmine = og * 4 + (b4 ? 2 : 0) + (b2 ? 1 : 0);
    const int jmine_s = hswz(jmine);          // swizzled store slot

    // weights: w2[jl][m] = {W[og*4+jl][kg*16+2m], W[og*4+jl][kg*16+2m+1]}
    u64t w2[4][8];
#pragma unroll
    for (int jl = 0; jl < 4; jl++) {
        const ulonglong2* wp =
            (const ulonglong2*)(Whh + (og * 4 + jl) * NH + kg * 16);
        ulonglong2 v0 = wp[0], v1 = wp[1], v2 = wp[2], v3 = wp[3];
        w2[jl][0] = v0.x; w2[jl][1] = v0.y;
        w2[jl][2] = v1.x; w2[jl][3] = v1.y;
        w2[jl][4] = v2.x; w2[jl][5] = v2.y;
        w2[jl][6] = v3.x; w2[jl][7] = v3.y;
    }

    if (tid < NH) hbuf[0][tid] = 0.f;   // zeros are swizzle-invariant
    __syncthreads();

    const float* __restrict__ xq = g_xp + (long)b * (NT * NH);

    int cur = 0;

    auto do_step = [&](float xv) {
        // chunk i (logical k = kg*16+4i..+3) lives at stored quad kg+8i
        // -> float offset 4*kg + 32*i. 8 kg lanes span 8 bank-quads: no
        // conflicts; 4 og-lanes per address broadcast for free.
        const float* hb = &hbuf[cur][0];
        ulonglong2 hv0 = *(const ulonglong2*)(hb + 4 * kg);
        ulonglong2 hv1 = *(const ulonglong2*)(hb + 4 * kg + 32);
        ulonglong2 hv2 = *(const ulonglong2*)(hb + 4 * kg + 64);
        ulonglong2 hv3 = *(const ulonglong2*)(hb + 4 * kg + 96);
        u64t hp[8] = {hv0.x, hv0.y, hv1.x, hv1.y, hv2.x, hv2.y, hv3.x, hv3.y};

        u64t c[4] = {0ull, 0ull, 0ull, 0ull};
#pragma unroll
        for (int i = 0; i < 8; i++) {
            ffma2(c[0], hp[i], w2[0][i]);
            ffma2(c[1], hp[i], w2[1][i]);
            ffma2(c[2], hp[i], w2[2][i]);
            ffma2(c[3], hp[i], w2[3][i]);
        }

        float s0, s1, s2, s3, lo, hi;
        unpack2(c[0], lo, hi); s0 = lo + hi;
        unpack2(c[1], lo, hi); s1 = lo + hi;
        unpack2(c[2], lo, hi); s2 = lo + hi;
        unpack2(c[3], lo, hi); s3 = lo + hi;

        // stage 1 (xor 4): keep outputs {2*b4, 2*b4+1}
        float keep0 = b4 ? s2 : s0;
        float send0 = b4 ? s0 : s2;
        float keep1 = b4 ? s3 : s1;
        float send1 = b4 ? s1 : s3;
        float t10 = keep0 + __shfl_xor_sync(0xffffffffu, send0, 4);
        float t11 = keep1 + __shfl_xor_sync(0xffffffffu, send1, 4);
        // stage 2 (xor 2): keep output 2*b4 + b2 (k1-parity partials)
        float keep2 = b2 ? t11 : t10;
        float send2 = b2 ? t10 : t11;
        float t2 = keep2 + __shfl_xor_sync(0xffffffffu, send2, 2);
        // stage 3 (xor 1): merge complementary slice halves (plain add)
        float tot = t2 + __shfl_xor_sync(0xffffffffu, t2, 1);

        int nxt = cur ^ 1;
        if (writer) hbuf[nxt][jmine_s] = tanh_fast(tot + xv);
        __syncthreads();
        cur = nxt;
    };

    // distance-4 prefetch pipeline (g_xp padded -> tail loads safe)
    float pf0 = xq[0 * NH + jmine];
    float pf1 = xq[1 * NH + jmine];
    float pf2 = xq[2 * NH + jmine];
    float pf3 = xq[3 * NH + jmine];

    for (int tb = 0; tb < NT; tb += 4) {
        float n0 = __ldg(&xq[(tb + 4) * NH + jmine]);
        float n1 = __ldg(&xq[(tb + 5) * NH + jmine]);
        float n2 = __ldg(&xq[(tb + 6) * NH + jmine]);
        float n3 = __ldg(&xq[(tb + 7) * NH + jmine]);

        do_step(pf0);
        do_step(pf1);
        do_step(pf2);
        do_step(pf3);

        pf0 = n0; pf1 = n1; pf2 = n2; pf3 = n3;
    }

    // fused FC (128 -> 2): warp 0 -> class 0, warp 1 -> class 1
    // (reads go through the swizzle map)
    if (tid < 64) {
        const int w = tid >> 5, lane = tid & 31;
        const float* h = &hbuf[cur][0];
        float s = 0.f;
#pragma unroll
        for (int kk = 0; kk < NH; kk += 32)
            s += h[hswz(kk + lane)] * fcw[w * NH + kk + lane];
#pragma unroll
        for (int off = 16; off > 0; off >>= 1)
            s += __shfl_xor_sync(0xffffffffu, s, off);
        if (lane == 0) out[b * 2 + w] = s + fcb[w];
    }
}

// ---------------------------------------------------------------------------
extern "C" void kernel_launch(void* const* d_in, const int* in_sizes, int n_in,
                              void* d_out, int out_size)
{
    const float* x   = (const float*)d_in[0];
    const float* Wih = (const float*)d_in[1];
    const float* Whh = (const float*)d_in[2];
    const float* bih = (const float*)d_in[3];
    const float* bhh = (const float*)d_in[4];
    const float* fcw = (const float*)d_in[5];
    const float* fcb = (const float*)d_in[6];
    float* out = (float*)d_out;

    (void)in_sizes; (void)n_in; (void)out_size;

    gemm_xp_kernel<<<(NB * NT) / BM, 256>>>(x, Wih, bih, bhh);
    rnn_scan_kernel<<<NB, 256>>>(Whh, fcw, fcb, out);
}

// round 17
// speedup vs baseline: 2.0704x; 1.0186x over previous
#include <cuda_runtime.h>
#include <cstdint>

#define NB 256
#define NT 512
#define NI 300
#define NH 128

typedef unsigned long long u64t;

// Precomputed input projections xp[b][t][h], padded by 8 timesteps so the
// distance-4 register prefetch in the scan can overrun harmlessly.
__device__ float g_xp[(NB * NT + 8) * NH];

// ---------------- packed f32x2 helpers (sm_103a) ----------------
__device__ __forceinline__ u64t pack2(float lo, float hi) {
    u64t r;
    asm("mov.b64 %0, {%1, %2};" : "=l"(r) : "f"(lo), "f"(hi));
    return r;
}
__device__ __forceinline__ void unpack2(u64t v, float& lo, float& hi) {
    asm("mov.b64 {%0, %1}, %2;" : "=f"(lo), "=f"(hi) : "l"(v));
}
__device__ __forceinline__ void ffma2(u64t& d, u64t a, u64t b) {
    asm("fma.rn.f32x2 %0, %1, %2, %0;" : "+l"(d) : "l"(a), "l"(b));
}
__device__ __forceinline__ void cp_async4(uint32_t s, const void* g) {
    asm volatile("cp.async.ca.shared.global [%0], [%1], 4;" :: "r"(s), "l"(g));
}
// fast tanh: 1 - 2/(e^{2x}+1) via MUFU ex2 + rcp (~1e-6 abs err)
__device__ __forceinline__ float tanh_fast(float x) {
    float e;
    asm("ex2.approx.f32 %0, %1;" : "=f"(e) : "f"(x * 2.885390082f));  // 2*log2(e)
    float r;
    asm("rcp.approx.f32 %0, %1;" : "=f"(r) : "f"(e + 1.0f));
    return fmaf(-2.0f, r, 1.0f);
}

// hbuf quad swizzle: logical float j -> stored float index (round-16; makes
// the kg-strided LDS.128 reads conflict-free).
__device__ __forceinline__ int hswz(int j) {
    int q = j >> 2;
    int P = (q >> 2) | ((q & 3) << 3);
    return (P << 2) | (j & 3);
}

// ---------------------------------------------------------------------------
// Phase 1: xp = x @ W_ih^T + (b_ih + b_hh)   — ROUND-6 VERSION (FROZEN:
// reworks in R9/R15 regressed via reg spills and operand bank conflicts)
// ---------------------------------------------------------------------------
#define BM 128
#define BN 128
#define BK 20
#define BMP (BM + 4)
#define NTILES (NI / BK)

__global__ __launch_bounds__(256, 2) void gemm_xp_kernel(
    const float* __restrict__ x, const float* __restrict__ Wih,
    const float* __restrict__ bih, const float* __restrict__ bhh)
{
    __shared__ __align__(16) float xs[2][BK][BMP];
    __shared__ __align__(16) float ws[2][BK][BMP];
    __shared__ float bias_s[NH];

    const int tid = threadIdx.x;
    const int m0 = blockIdx.x * BM;
    if (tid < NH) bias_s[tid] = bih[tid] + bhh[tid];

    const int tr = tid >> 4;
    const int tc = tid & 15;

    uint32_t offS[10];
    int offG[10];
#pragma unroll
    for (int it = 0; it < 10; it++) {
        int idx = tid + it * 256;
        int r = idx / BK, kk = idx % BK;
        offS[it] = (uint32_t)(kk * BMP + r) * 4u;
        offG[it] = r * NI + kk;
    }

    const uint32_t xsb0 = (uint32_t)__cvta_generic_to_shared(&xs[0][0][0]);
    const uint32_t xsb1 = (uint32_t)__cvta_generic_to_shared(&xs[1][0][0]);
    const uint32_t wsb0 = (uint32_t)__cvta_generic_to_shared(&ws[0][0][0]);
    const uint32_t wsb1 = (uint32_t)__cvta_generic_to_shared(&ws[1][0][0]);

    const float* xg = x + (long)m0 * NI;

    u64t acc2[8][4];
#pragma unroll
    for (int i = 0; i < 8; i++)
#pragma unroll
        for (int p = 0; p < 4; p++) acc2[i][p] = 0ull;

#define ISSUE_TILE(tile, xsb, wsb)                                   \
    do {                                                             \
        const float* xt_ = xg + (tile) * BK;                         \
        const float* wt_ = Wih + (tile) * BK;                        \
        _Pragma("unroll")                                            \
        for (int it = 0; it < 10; it++) {                            \
            cp_async4((xsb) + offS[it], xt_ + offG[it]);             \
            cp_async4((wsb) + offS[it], wt_ + offG[it]);             \
        }                                                            \
        asm volatile("cp.async.commit_group;");                      \
    } while (0)

    ISSUE_TILE(0, xsb0, wsb0);

    for (int tile = 0; tile < NTILES; tile++) {
        int buf = tile & 1;
        if (tile + 1 < NTILES) {
            if (buf == 0) ISSUE_TILE(tile + 1, xsb1, wsb1);
            else          ISSUE_TILE(tile + 1, xsb0, wsb0);
            asm volatile("cp.async.wait_group 1;");
        } else {
            asm volatile("cp.async.wait_group 0;");
        }
        __syncthreads();

        const float(*xsp)[BMP] = xs[buf];
        const float(*wsp)[BMP] = ws[buf];
#pragma unroll 4
        for (int kk = 0; kk < BK; kk++) {
            float4 a0 = *(const float4*)&xsp[kk][tr * 8];
            float4 a1 = *(const float4*)&xsp[kk][tr * 8 + 4];
            ulonglong2 bq0 = *(const ulonglong2*)&wsp[kk][tc * 8];
            ulonglong2 bq1 = *(const ulonglong2*)&wsp[kk][tc * 8 + 4];
            u64t bp[4] = {bq0.x, bq0.y, bq1.x, bq1.y};
            float av[8] = {a0.x, a0.y, a0.z, a0.w, a1.x, a1.y, a1.z, a1.w};
#pragma unroll
            for (int i = 0; i < 8; i++) {
                u64t ap = pack2(av[i], av[i]);
#pragma unroll
                for (int p = 0; p < 4; p++)
                    ffma2(acc2[i][p], ap, bp[p]);
            }
        }
        __syncthreads();
    }
#undef ISSUE_TILE

#pragma unroll
    for (int i = 0; i < 8; i++) {
        int r = m0 + tr * 8 + i;
        float* pdst = &g_xp[r * NH + tc * 8];
#pragma unroll
        for (int p = 0; p < 4; p++) {
            float lo, hi;
            unpack2(acc2[i][p], lo, hi);
            float2 v;
            v.x = lo + bias_s[tc * 8 + 2 * p];
            v.y = hi + bias_s[tc * 8 + 2 * p + 1];
            *(float2*)(pdst + 2 * p) = v;
        }
    }
}

// ---------------------------------------------------------------------------
// Phase 2: scan. TWO batch rows per CTA, 128 CTAs x 256 threads (1 CTA/SM).
// ROUND-17: both rows advance in the SAME threads within one barrier period:
// two independent dependency chains (rows share W_hh registers) interleave
// -> guaranteed ILP-2 on the serial path (LDS 29, FFMA chains, SHFL 26,
// MUFU) and ONE __syncthreads serves BOTH rows.
// Per thread per step-pair: 8 LDS.128 (conflict-free via hswz) + 64 FFMA2
// (8 chains of 8) + 8 SHFL (two interleaved 3-stage butterflies) + 2 tanh
// + 2 STS + 1 BAR; xp via distance-4 named-register prefetch, 2 streams.
// ---------------------------------------------------------------------------
__global__ __launch_bounds__(256, 1) void rnn_scan_kernel(
    const float* __restrict__ Whh, const float* __restrict__ fcw,
    const float* __restrict__ fcb, float* __restrict__ out)
{
    __shared__ __align__(16) float hbuf[2][2][NH];   // [pingpong][row][j_swz]

    const int tid = threadIdx.x;
    const int og = tid >> 3;        // 0..31: outputs og*4 .. +3
    const int kg = tid & 7;         // 0..7:  k-slice kg*16 .. +15
    const int b = blockIdx.x;       // rows 2b, 2b+1

    const bool b4 = (kg & 4) != 0;
    const bool b2 = (kg & 2) != 0;
    const bool writer = (kg & 1) == 0;
    const int jmine = og * 4 + (b4 ? 2 : 0) + (b2 ? 1 : 0);
    const int jmine_s = hswz(jmine);

    // weights (SHARED by both rows): w2[jl][m] covers k = kg*16 + 2m (+1)
    u64t w2[4][8];
#pragma unroll
    for (int jl = 0; jl < 4; jl++) {
        const ulonglong2* wp =
            (const ulonglong2*)(Whh + (og * 4 + jl) * NH + kg * 16);
        ulonglong2 v0 = wp[0], v1 = wp[1], v2 = wp[2], v3 = wp[3];
        w2[jl][0] = v0.x; w2[jl][1] = v0.y;
        w2[jl][2] = v1.x; w2[jl][3] = v1.y;
        w2[jl][4] = v2.x; w2[jl][5] = v2.y;
        w2[jl][6] = v3.x; w2[jl][7] = v3.y;
    }

    hbuf[0][tid >> 7][tid & 127] = 0.f;   // zeros are swizzle-invariant
    __syncthreads();

    const float* __restrict__ xqA = g_xp + (long)(2 * b) * (NT * NH);
    const float* __restrict__ xqB = xqA + (long)(NT * NH);

    int cur = 0;

    auto do_step_pair = [&](float xvA, float xvB) {
        const float* hA = &hbuf[cur][0][0];
        const float* hB = &hbuf[cur][1][0];
        // conflict-free swizzled loads; A and B chains independent
        ulonglong2 a0 = *(const ulonglong2*)(hA + 4 * kg);
        ulonglong2 a1 = *(const ulonglong2*)(hA + 4 * kg + 32);
        ulonglong2 a2 = *(const ulonglong2*)(hA + 4 * kg + 64);
        ulonglong2 a3 = *(const ulonglong2*)(hA + 4 * kg + 96);
        ulonglong2 e0 = *(const ulonglong2*)(hB + 4 * kg);
        ulonglong2 e1 = *(const ulonglong2*)(hB + 4 * kg + 32);
        ulonglong2 e2 = *(const ulonglong2*)(hB + 4 * kg + 64);
        ulonglong2 e3 = *(const ulonglong2*)(hB + 4 * kg + 96);
        u64t hpA[8] = {a0.x, a0.y, a1.x, a1.y, a2.x, a2.y, a3.x, a3.y};
        u64t hpB[8] = {e0.x, e0.y, e1.x, e1.y, e2.x, e2.y, e3.x, e3.y};

        u64t cA[4] = {0ull, 0ull, 0ull, 0ull};
        u64t cB[4] = {0ull, 0ull, 0ull, 0ull};
#pragma unroll
        for (int i = 0; i < 8; i++) {
            ffma2(cA[0], hpA[i], w2[0][i]);
            ffma2(cB[0], hpB[i], w2[0][i]);
            ffma2(cA[1], hpA[i], w2[1][i]);
            ffma2(cB[1], hpB[i], w2[1][i]);
            ffma2(cA[2], hpA[i], w2[2][i]);
            ffma2(cB[2], hpB[i], w2[2][i]);
            ffma2(cA[3], hpA[i], w2[3][i]);
            ffma2(cB[3], hpB[i], w2[3][i]);
        }

        float lo, hi;
        float sA0, sA1, sA2, sA3, sB0, sB1, sB2, sB3;
        unpack2(cA[0], lo, hi); sA0 = lo + hi;
        unpack2(cB[0], lo, hi); sB0 = lo + hi;
        unpack2(cA[1], lo, hi); sA1 = lo + hi;
        unpack2(cB[1], lo, hi); sB1 = lo + hi;
        unpack2(cA[2], lo, hi); sA2 = lo + hi;
        unpack2(cB[2], lo, hi); sB2 = lo + hi;
        unpack2(cA[3], lo, hi); sA3 = lo + hi;
        unpack2(cB[3], lo, hi); sB3 = lo + hi;

        // two interleaved 3-stage butterflies (independent chains)
        // stage 1 (xor 4)
        float kA0 = b4 ? sA2 : sA0, dA0 = b4 ? sA0 : sA2;
        float kA1 = b4 ? sA3 : sA1, dA1 = b4 ? sA1 : sA3;
        float kB0 = b4 ? sB2 : sB0, dB0 = b4 ? sB0 : sB2;
        float kB1 = b4 ? sB3 : sB1, dB1 = b4 ? sB1 : sB3;
        float tA0 = kA0 + __shfl_xor_sync(0xffffffffu, dA0, 4);
        float tB0 = kB0 + __shfl_xor_sync(0xffffffffu, dB0, 4);
        float tA1 = kA1 + __shfl_xor_sync(0xffffffffu, dA1, 4);
        float tB1 = kB1 + __shfl_xor_sync(0xffffffffu, dB1, 4);
        // stage 2 (xor 2)
        float kA2 = b2 ? tA1 : tA0, dA2 = b2 ? tA0 : tA1;
        float kB2 = b2 ? tB1 : tB0, dB2 = b2 ? tB0 : tB1;
        float tA2 = kA2 + __shfl_xor_sync(0xffffffffu, dA2, 2);
        float tB2 = kB2 + __shfl_xor_sync(0xffffffffu, dB2, 2);
        // stage 3 (xor 1): plain merge of complementary halves
        float totA = tA2 + __shfl_xor_sync(0xffffffffu, tA2, 1);
        float totB = tB2 + __shfl_xor_sync(0xffffffffu, tB2, 1);

        int nxt = cur ^ 1;
        if (writer) {
            hbuf[nxt][0][jmine_s] = tanh_fast(totA + xvA);
            hbuf[nxt][1][jmine_s] = tanh_fast(totB + xvB);
        }
        __syncthreads();
        cur = nxt;
    };

    // distance-4 prefetch pipeline, two streams (g_xp padded -> tail safe)
    float pA0 = xqA[0 * NH + jmine], pB0 = xqB[0 * NH + jmine];
    float pA1 = xqA[1 * NH + jmine], pB1 = xqB[1 * NH + jmine];
    float pA2 = xqA[2 * NH + jmine], pB2 = xqB[2 * NH + jmine];
    float pA3 = xqA[3 * NH + jmine], pB3 = xqB[3 * NH + jmine];

    for (int tb = 0; tb < NT; tb += 4) {
        float nA0 = __ldg(&xqA[(tb + 4) * NH + jmine]);
        float nB0 = __ldg(&xqB[(tb + 4) * NH + jmine]);
        float nA1 = __ldg(&xqA[(tb + 5) * NH + jmine]);
        float nB1 = __ldg(&xqB[(tb + 5) * NH + jmine]);
        float nA2 = __ldg(&xqA[(tb + 6) * NH + jmine]);
        float nB2 = __ldg(&xqB[(tb + 6) * NH + jmine]);
        float nA3 = __ldg(&xqA[(tb + 7) * NH + jmine]);
        float nB3 = __ldg(&xqB[(tb + 7) * NH + jmine]);

        do_step_pair(pA0, pB0);
        do_step_pair(pA1, pB1);
        do_step_pair(pA2, pB2);
        do_step_pair(pA3, pB3);

        pA0 = nA0; pA1 = nA1; pA2 = nA2; pA3 = nA3;
        pB0 = nB0; pB1 = nB1; pB2 = nB2; pB3 = nB3;
    }

    // fused FC (128 -> 2): warp w -> (row = w>>1, class = w&1)
    if (tid < 128) {
        const int w = tid >> 5, lane = tid & 31;
        const int frow = w >> 1, cls = w & 1;
        const float* h = &hbuf[cur][frow][0];
        float s = 0.f;
#pragma unroll
        for (int kk = 0; kk < NH; kk += 32)
            s += h[hswz(kk + lane)] * fcw[cls * NH + kk + lane];
#pragma unroll
        for (int off = 16; off > 0; off >>= 1)
            s += __shfl_xor_sync(0xffffffffu, s, off);
        if (lane == 0) out[(2 * b + frow) * 2 + cls] = s + fcb[cls];
    }
}

// ---------------------------------------------------------------------------
extern "C" void kernel_launch(void* const* d_in, const int* in_sizes, int n_in,
                              void* d_out, int out_size)
{
    const float* x   = (const float*)d_in[0];
    const float* Wih = (const float*)d_in[1];
    const float* Whh = (const float*)d_in[2];
    const float* bih = (const float*)d_in[3];
    const float* bhh = (const float*)d_in[4];
    const float* fcw = (const float*)d_in[5];
    const float* fcb = (const float*)d_in[6];
    float* out = (float*)d_out;

    (void)in_sizes; (void)n_in; (void)out_size;

    gemm_xp_kernel<<<(NB * NT) / BM, 256>>>(x, Wih, bih, bhh);
    rnn_scan_kernel<<<NB / 2, 256>>>(Whh, fcw, fcb, out);
}